// round 2
// baseline (speedup 1.0000x reference)
#include <cuda_runtime.h>
#include <cstdint>

#define NNODES 16384
#define IN_F 128
#define PSI_F 16
#define H1 15
#define H2 25
#define OUT_F 128

#define JCHUNKS 16
#define JSZ 1024
#define AGG_THREADS 256
#define COLS_PER_THREAD 4

__device__ float g_h[NNODES * PSI_F];                    // 1 MB
__device__ float g_part[(size_t)JCHUNKS * 17 * NNODES];  // 17.8 MB [jc][k:0..15 feat,16 count][i]

// ---------------------------------------------------------------------------
// Kernel A: psi MLP. 4 threads per node, 64 nodes per block, 256 blocks.
// ---------------------------------------------------------------------------
__global__ void __launch_bounds__(256) psi_kernel(
    const float* __restrict__ nodes,
    const float* __restrict__ w1, const float* __restrict__ b1,
    const float* __restrict__ w2, const float* __restrict__ b2)
{
    __shared__ float w1s[IN_F * H1];                 // 7.7 KB
    __shared__ float w2s[H1 * PSI_F];
    __shared__ float b1s[H1];
    __shared__ float b2s[PSI_F];
    __shared__ __align__(16) float xs[64 * 132];     // 33.8 KB, stride 132 (16B-aligned rows)

    const int tid = threadIdx.x;
    const int n0 = blockIdx.x * 64;
    const int nl = tid >> 2;      // local node 0..63
    const int part = tid & 3;     // feature quarter

    for (int i = tid; i < IN_F * H1; i += 256) w1s[i] = w1[i];
    for (int i = tid; i < H1 * PSI_F; i += 256) w2s[i] = w2[i];
    if (tid < H1) b1s[tid] = b1[tid];
    if (tid >= 32 && tid < 32 + PSI_F) b2s[tid - 32] = b2[tid - 32];

    // stage 64 nodes x 128 feats via float4
    for (int idx = tid; idx < 64 * 32; idx += 256) {
        int node = idx >> 5, c4 = idx & 31;
        float4 v = reinterpret_cast<const float4*>(nodes + (size_t)(n0 + node) * IN_F)[c4];
        *reinterpret_cast<float4*>(xs + node * 132 + c4 * 4) = v;
    }
    __syncthreads();

    float t[H1];
#pragma unroll
    for (int r = 0; r < H1; r++) t[r] = 0.f;

    const float* xrow = xs + nl * 132 + part * 32;
#pragma unroll 8
    for (int f = 0; f < 32; f++) {
        int fi = (f + part) & 31;                    // rotation -> conflict-free banks
        float xv = xrow[fi];
        const float* wr = w1s + (part * 32 + fi) * H1;
#pragma unroll
        for (int r = 0; r < H1; r++) t[r] = fmaf(xv, wr[r], t[r]);
    }
    // reduce across the 4 parts of this node
#pragma unroll
    for (int r = 0; r < H1; r++) {
        t[r] += __shfl_xor_sync(0xFFFFFFFFu, t[r], 1);
        t[r] += __shfl_xor_sync(0xFFFFFFFFu, t[r], 2);
        t[r] = fmaxf(t[r] + b1s[r], 0.f);
    }

    // layer 2: each part produces 4 of the 16 outputs -> coalesced float4 store
    float hv[4];
#pragma unroll
    for (int q = 0; q < 4; q++) hv[q] = b2s[part * 4 + q];
#pragma unroll
    for (int r = 0; r < H1; r++) {
#pragma unroll
        for (int q = 0; q < 4; q++)
            hv[q] = fmaf(t[r], w2s[r * PSI_F + part * 4 + q], hv[q]);
    }
    float4 v;
    v.x = fmaxf(hv[0], 0.f); v.y = fmaxf(hv[1], 0.f);
    v.z = fmaxf(hv[2], 0.f); v.w = fmaxf(hv[3], 0.f);
    *reinterpret_cast<float4*>(g_h + (size_t)(n0 + nl) * PSI_F + part * 4) = v;
}

// ---------------------------------------------------------------------------
// Kernel B: aggregation. Predicated packed f32x2 adds: 2 cols per asm block.
// ---------------------------------------------------------------------------
__device__ __forceinline__ void pred_add2_2col(
    unsigned long long* a0, unsigned long long* a1,
    const unsigned long long* h, int x0, int x1)
{
    asm volatile(
        "{\n\t"
        ".reg .pred p0, p1;\n\t"
        "setp.ne.s32 p0, %24, 0;\n\t"
        "setp.ne.s32 p1, %25, 0;\n\t"
        "@p0 add.rn.f32x2 %0, %0, %16;\n\t"
        "@p0 add.rn.f32x2 %1, %1, %17;\n\t"
        "@p0 add.rn.f32x2 %2, %2, %18;\n\t"
        "@p0 add.rn.f32x2 %3, %3, %19;\n\t"
        "@p0 add.rn.f32x2 %4, %4, %20;\n\t"
        "@p0 add.rn.f32x2 %5, %5, %21;\n\t"
        "@p0 add.rn.f32x2 %6, %6, %22;\n\t"
        "@p0 add.rn.f32x2 %7, %7, %23;\n\t"
        "@p1 add.rn.f32x2 %8, %8, %16;\n\t"
        "@p1 add.rn.f32x2 %9, %9, %17;\n\t"
        "@p1 add.rn.f32x2 %10, %10, %18;\n\t"
        "@p1 add.rn.f32x2 %11, %11, %19;\n\t"
        "@p1 add.rn.f32x2 %12, %12, %20;\n\t"
        "@p1 add.rn.f32x2 %13, %13, %21;\n\t"
        "@p1 add.rn.f32x2 %14, %14, %22;\n\t"
        "@p1 add.rn.f32x2 %15, %15, %23;\n\t"
        "}"
        : "+l"(a0[0]), "+l"(a0[1]), "+l"(a0[2]), "+l"(a0[3]),
          "+l"(a0[4]), "+l"(a0[5]), "+l"(a0[6]), "+l"(a0[7]),
          "+l"(a1[0]), "+l"(a1[1]), "+l"(a1[2]), "+l"(a1[3]),
          "+l"(a1[4]), "+l"(a1[5]), "+l"(a1[6]), "+l"(a1[7])
        : "l"(h[0]), "l"(h[1]), "l"(h[2]), "l"(h[3]),
          "l"(h[4]), "l"(h[5]), "l"(h[6]), "l"(h[7]),
          "r"(x0), "r"(x1));
}

__global__ void __launch_bounds__(AGG_THREADS, 2) agg_kernel(const int* __restrict__ A)
{
    const int tid = threadIdx.x;
    const int icol0 = blockIdx.x * (AGG_THREADS * COLS_PER_THREAD) + tid * COLS_PER_THREAD;
    const int j0 = blockIdx.y * JSZ;

    __shared__ __align__(16) float hs[256][PSI_F];   // 16 KB

    unsigned long long acc[32];
#pragma unroll
    for (int p = 0; p < 32; p++) acc[p] = 0ull;
    int cnt[COLS_PER_THREAD] = {0, 0, 0, 0};

    for (int js = 0; js < JSZ; js += 256) {
        __syncthreads();
        {
            const float4* src = reinterpret_cast<const float4*>(&g_h[(size_t)(j0 + js) * PSI_F]);
            float4* dst = reinterpret_cast<float4*>(&hs[0][0]);
            for (int idx = tid; idx < 256 * PSI_F / 4; idx += AGG_THREADS) dst[idx] = src[idx];
        }
        __syncthreads();

        const int* Ap = A + (size_t)(j0 + js) * NNODES + icol0;
#pragma unroll 8
        for (int jj = 0; jj < 256; jj++) {
            int4 a4 = *reinterpret_cast<const int4*>(Ap);
            Ap += NNODES;

            const ulonglong2* hp = reinterpret_cast<const ulonglong2*>(&hs[jj][0]);
            ulonglong2 q0 = hp[0], q1 = hp[1], q2 = hp[2], q3 = hp[3];
            unsigned long long h2[8] = {q0.x, q0.y, q1.x, q1.y, q2.x, q2.y, q3.x, q3.y};

            cnt[0] += a4.x; cnt[1] += a4.y; cnt[2] += a4.z; cnt[3] += a4.w;
            pred_add2_2col(&acc[0],  &acc[8],  h2, a4.x, a4.y);
            pred_add2_2col(&acc[16], &acc[24], h2, a4.z, a4.w);
        }
    }

    const size_t base = (size_t)blockIdx.y * 17 * NNODES + icol0;
#pragma unroll
    for (int c = 0; c < COLS_PER_THREAD; c++) {
#pragma unroll
        for (int p = 0; p < 8; p++) {
            unsigned long long v = acc[c * 8 + p];
            g_part[base + (size_t)(2 * p) * NNODES + c] =
                __uint_as_float((unsigned int)(v & 0xFFFFFFFFull));
            g_part[base + (size_t)(2 * p + 1) * NNODES + c] =
                __uint_as_float((unsigned int)(v >> 32));
        }
        g_part[base + (size_t)16 * NNODES + c] = (float)cnt[c];
    }
}

// ---------------------------------------------------------------------------
// Kernel C: reduce partials + fi MLP. 2 threads/node phase 1, 128 nodes/block.
// ---------------------------------------------------------------------------
__global__ void __launch_bounds__(256) fin_kernel(
    const float* __restrict__ nodes,
    const float* __restrict__ w1, const float* __restrict__ b1,
    const float* __restrict__ w2, const float* __restrict__ b2,
    float* __restrict__ out)
{
    __shared__ float ws[(IN_F + PSI_F) * H2];        // 14.4 KB
    __shared__ float b1s[H2];
    __shared__ float xs[128 * 33];                   // 16.9 KB (32-feat chunk, stride 33)
    __shared__ float gs[128 * 26];                   // 13.3 KB

    const int tid = threadIdx.x;
    const int n0 = blockIdx.x * 128;
    const int nl = tid >> 1;       // local node 0..127
    const int half = tid & 1;      // feature half
    const int node = n0 + nl;

    for (int i = tid; i < (IN_F + PSI_F) * H2; i += 256) ws[i] = w1[i];
    if (tid < H2) b1s[tid] = b1[tid];

    float g[H2];
#pragma unroll
    for (int r = 0; r < H2; r++) g[r] = 0.f;

    // x part: 4 chunks of 32 feats; each thread handles 16 feats per chunk
    for (int cf = 0; cf < 4; cf++) {
        __syncthreads();
        for (int idx = tid; idx < 128 * 32; idx += 256) {
            int nn = idx >> 5, f = idx & 31;
            xs[nn * 33 + f] = nodes[(size_t)(n0 + nn) * IN_F + cf * 32 + f];
        }
        __syncthreads();
#pragma unroll 4
        for (int f = 0; f < 16; f++) {
            float xv = xs[nl * 33 + half * 16 + f];
            const float* wr = ws + (cf * 32 + half * 16 + f) * H2;
#pragma unroll
            for (int r = 0; r < H2; r++) g[r] = fmaf(xv, wr[r], g[r]);
        }
    }

    // psi part: each thread handles 8 of the 16 psi features
    float cntv = 0.f;
#pragma unroll
    for (int jc = 0; jc < JCHUNKS; jc++)
        cntv += g_part[((size_t)jc * 17 + 16) * NNODES + node];
    float inv = 1.f / cntv;

#pragma unroll
    for (int kk = 0; kk < 8; kk++) {
        int k = half * 8 + kk;
        float s = 0.f;
#pragma unroll
        for (int jc = 0; jc < JCHUNKS; jc++)
            s += g_part[((size_t)jc * 17 + k) * NNODES + node];
        s *= inv;
        const float* wr = ws + (IN_F + k) * H2;
#pragma unroll
        for (int r = 0; r < H2; r++) g[r] = fmaf(s, wr[r], g[r]);
    }

    // combine halves, relu, stash
#pragma unroll
    for (int r = 0; r < H2; r++) g[r] += __shfl_xor_sync(0xFFFFFFFFu, g[r], 1);
    if (half == 0) {
#pragma unroll
        for (int r = 0; r < H2; r++) gs[nl * 26 + r] = fmaxf(g[r] + b1s[r], 0.f);
    }
    __syncthreads();

    // phase 2: thread = (output channel, node half); 64 outputs each, coalesced STG
    const int ch = tid & 127;
    const int nh = tid >> 7;
    float w2r[H2];
#pragma unroll
    for (int r = 0; r < H2; r++) w2r[r] = w2[r * OUT_F + ch];
    const float b2v = b2[ch];

#pragma unroll 2
    for (int n = 0; n < 64; n++) {
        int nn = nh * 64 + n;
        float o = b2v;
#pragma unroll
        for (int r = 0; r < H2; r++) o = fmaf(gs[nn * 26 + r], w2r[r], o);
        out[(size_t)(n0 + nn) * OUT_F + ch] = fmaxf(o, 0.f);
    }
}

// ---------------------------------------------------------------------------
extern "C" void kernel_launch(void* const* d_in, const int* in_sizes, int n_in,
                              void* d_out, int out_size)
{
    const float* nodes  = (const float*)d_in[0];
    const int*   adj    = (const int*)  d_in[1];
    const float* psi_w1 = (const float*)d_in[2];
    const float* psi_b1 = (const float*)d_in[3];
    const float* psi_w2 = (const float*)d_in[4];
    const float* psi_b2 = (const float*)d_in[5];
    const float* fi_w1  = (const float*)d_in[6];
    const float* fi_b1  = (const float*)d_in[7];
    const float* fi_w2  = (const float*)d_in[8];
    const float* fi_b2  = (const float*)d_in[9];
    float* out = (float*)d_out;

    psi_kernel<<<NNODES / 64, 256>>>(nodes, psi_w1, psi_b1, psi_w2, psi_b2);
    agg_kernel<<<dim3(NNODES / (AGG_THREADS * COLS_PER_THREAD), JCHUNKS), AGG_THREADS>>>(adj);
    fin_kernel<<<NNODES / 128, 256>>>(nodes, fi_w1, fi_b1, fi_w2, fi_b2, out);
}

// round 4
// speedup vs baseline: 1.3601x; 1.3601x over previous
#include <cuda_runtime.h>
#include <cstdint>

#define NNODES 16384
#define IN_F 128
#define PSI_F 16
#define H1 15
#define H2 25
#define OUT_F 128

#define JC 37                 // j-chunks: 16 i-tiles x 37 = 592 = 148 SMs x 2 resident x 2 waves
#define CHUNK 443             // rows per chunk (last chunk = 436)
#define AGG_THREADS 256
#define CPT 4                 // adjacency columns per thread (one int4)

__device__ float g_h[NNODES * PSI_F];                  // 1 MB   [node][f]
__device__ float g_part[(size_t)JC * 17 * NNODES];     // 41 MB  [jc][k(0..15 feat,16 cnt)][i]

// ---------------------------------------------------------------------------
// Kernel A: psi MLP. 4 threads/node, 32 nodes/block, 512 blocks.
// ---------------------------------------------------------------------------
__global__ void __launch_bounds__(128) psi_kernel(
    const float* __restrict__ nodes,
    const float* __restrict__ w1, const float* __restrict__ b1,
    const float* __restrict__ w2, const float* __restrict__ b2)
{
    __shared__ float w1s[IN_F * H1];
    __shared__ float w2s[H1 * PSI_F];
    __shared__ float b1s[H1];
    __shared__ float b2s[PSI_F];
    __shared__ __align__(16) float xs[32 * 132];

    const int tid = threadIdx.x;
    const int n0 = blockIdx.x * 32;
    const int nl = tid >> 2;
    const int part = tid & 3;

    for (int i = tid; i < IN_F * H1; i += 128) w1s[i] = w1[i];
    for (int i = tid; i < H1 * PSI_F; i += 128) w2s[i] = w2[i];
    if (tid < H1) b1s[tid] = b1[tid];
    if (tid >= 32 && tid < 32 + PSI_F) b2s[tid - 32] = b2[tid - 32];

    for (int idx = tid; idx < 32 * 32; idx += 128) {
        int node = idx >> 5, c4 = idx & 31;
        float4 v = reinterpret_cast<const float4*>(nodes + (size_t)(n0 + node) * IN_F)[c4];
        *reinterpret_cast<float4*>(xs + node * 132 + c4 * 4) = v;
    }
    __syncthreads();

    float t[H1];
#pragma unroll
    for (int r = 0; r < H1; r++) t[r] = 0.f;

    const float* xrow = xs + nl * 132 + part * 32;
#pragma unroll 8
    for (int f = 0; f < 32; f++) {
        int fi = (f + part) & 31;                    // bank-rotation
        float xv = xrow[fi];
        const float* wr = w1s + (part * 32 + fi) * H1;
#pragma unroll
        for (int r = 0; r < H1; r++) t[r] = fmaf(xv, wr[r], t[r]);
    }
#pragma unroll
    for (int r = 0; r < H1; r++) {
        t[r] += __shfl_xor_sync(0xFFFFFFFFu, t[r], 1);
        t[r] += __shfl_xor_sync(0xFFFFFFFFu, t[r], 2);
        t[r] = fmaxf(t[r] + b1s[r], 0.f);
    }

    float hv[4];
#pragma unroll
    for (int q = 0; q < 4; q++) hv[q] = b2s[part * 4 + q];
#pragma unroll
    for (int r = 0; r < H1; r++) {
#pragma unroll
        for (int q = 0; q < 4; q++)
            hv[q] = fmaf(t[r], w2s[r * PSI_F + part * 4 + q], hv[q]);
    }
    float4 v;
    v.x = fmaxf(hv[0], 0.f); v.y = fmaxf(hv[1], 0.f);
    v.z = fmaxf(hv[2], 0.f); v.w = fmaxf(hv[3], 0.f);
    *reinterpret_cast<float4*>(g_h + (size_t)(n0 + nl) * PSI_F + part * 4) = v;
}

// ---------------------------------------------------------------------------
// Kernel B: aggregation. FFMA2 accumulation, exact-wave grid (16 x 37).
// ---------------------------------------------------------------------------
__device__ __forceinline__ void ffma2(unsigned long long& d,
                                      unsigned long long a,
                                      unsigned long long b)
{
    asm("fma.rn.f32x2 %0, %1, %2, %0;" : "+l"(d) : "l"(a), "l"(b));
}

__global__ void __launch_bounds__(AGG_THREADS, 2) agg_kernel(const int* __restrict__ A)
{
    __shared__ __align__(16) float hs[256][PSI_F];   // 16 KB

    const int tid = threadIdx.x;
    const int icol0 = blockIdx.x * (AGG_THREADS * CPT) + tid * CPT;
    const int jc = blockIdx.y;
    const int jstart = jc * CHUNK;
    const int len = (jc == JC - 1) ? (NNODES - (JC - 1) * CHUNK) : CHUNK;

    unsigned long long acc[32];
#pragma unroll
    for (int p = 0; p < 32; p++) acc[p] = 0ull;
    int cnt[CPT] = {0, 0, 0, 0};

    for (int js = 0; js < len; js += 256) {
        const int sl = min(256, len - js);
        __syncthreads();
        {
            const float4* src = reinterpret_cast<const float4*>(
                &g_h[(size_t)(jstart + js) * PSI_F]);
            float4* dst = reinterpret_cast<float4*>(&hs[0][0]);
            for (int idx = tid; idx < sl * 4; idx += AGG_THREADS) dst[idx] = src[idx];
        }
        __syncthreads();

        const int* Ap = A + (size_t)(jstart + js) * NNODES + icol0;
#pragma unroll 4
        for (int jj = 0; jj < sl; jj++) {
            int4 a4 = *reinterpret_cast<const int4*>(Ap);
            Ap += NNODES;

            const ulonglong2* hp = reinterpret_cast<const ulonglong2*>(&hs[jj][0]);
            ulonglong2 q0 = hp[0], q1 = hp[1], q2 = hp[2], q3 = hp[3];
            unsigned long long h2[8] = {q0.x, q0.y, q1.x, q1.y, q2.x, q2.y, q3.x, q3.y};

            {
                unsigned b = ((unsigned)(-a4.x)) & 0x3F800000u;
                unsigned long long m2;
                asm("mov.b64 %0, {%1, %1};" : "=l"(m2) : "r"(b));
                cnt[0] += a4.x;
#pragma unroll
                for (int p = 0; p < 8; p++) ffma2(acc[p], h2[p], m2);
            }
            {
                unsigned b = ((unsigned)(-a4.y)) & 0x3F800000u;
                unsigned long long m2;
                asm("mov.b64 %0, {%1, %1};" : "=l"(m2) : "r"(b));
                cnt[1] += a4.y;
#pragma unroll
                for (int p = 0; p < 8; p++) ffma2(acc[8 + p], h2[p], m2);
            }
            {
                unsigned b = ((unsigned)(-a4.z)) & 0x3F800000u;
                unsigned long long m2;
                asm("mov.b64 %0, {%1, %1};" : "=l"(m2) : "r"(b));
                cnt[2] += a4.z;
#pragma unroll
                for (int p = 0; p < 8; p++) ffma2(acc[16 + p], h2[p], m2);
            }
            {
                unsigned b = ((unsigned)(-a4.w)) & 0x3F800000u;
                unsigned long long m2;
                asm("mov.b64 %0, {%1, %1};" : "=l"(m2) : "r"(b));
                cnt[3] += a4.w;
#pragma unroll
                for (int p = 0; p < 8; p++) ffma2(acc[24 + p], h2[p], m2);
            }
        }
    }

    // vectorized partial writes: [jc][k][i], STG.128 fully coalesced
    const size_t base = (size_t)jc * 17 * NNODES + icol0;
#pragma unroll
    for (int p = 0; p < 8; p++) {
        float4 lo, hi;
        lo.x = __uint_as_float((unsigned)(acc[p]       & 0xFFFFFFFFull));
        lo.y = __uint_as_float((unsigned)(acc[8 + p]   & 0xFFFFFFFFull));
        lo.z = __uint_as_float((unsigned)(acc[16 + p]  & 0xFFFFFFFFull));
        lo.w = __uint_as_float((unsigned)(acc[24 + p]  & 0xFFFFFFFFull));
        hi.x = __uint_as_float((unsigned)(acc[p]      >> 32));
        hi.y = __uint_as_float((unsigned)(acc[8 + p]  >> 32));
        hi.z = __uint_as_float((unsigned)(acc[16 + p] >> 32));
        hi.w = __uint_as_float((unsigned)(acc[24 + p] >> 32));
        *reinterpret_cast<float4*>(&g_part[base + (size_t)(2 * p) * NNODES]) = lo;
        *reinterpret_cast<float4*>(&g_part[base + (size_t)(2 * p + 1) * NNODES]) = hi;
    }
    {
        float4 cv;
        cv.x = (float)cnt[0]; cv.y = (float)cnt[1];
        cv.z = (float)cnt[2]; cv.w = (float)cnt[3];
        *reinterpret_cast<float4*>(&g_part[base + (size_t)16 * NNODES]) = cv;
    }
}

// ---------------------------------------------------------------------------
// Kernel C: reduce partials + fi MLP. 4 thr/node phase 1, 32 nodes/block.
// ---------------------------------------------------------------------------
__global__ void __launch_bounds__(128) fin_kernel(
    const float* __restrict__ nodes,
    const float* __restrict__ w1, const float* __restrict__ b1,
    const float* __restrict__ w2, const float* __restrict__ b2,
    float* __restrict__ out)
{
    __shared__ float ws[(IN_F + PSI_F) * H2];        // 14.4 KB
    __shared__ float b1s[H2];
    __shared__ float xs[32 * 33];
    __shared__ float gs[32 * 26];

    const int tid = threadIdx.x;
    const int n0 = blockIdx.x * 32;
    const int nl = tid >> 2;
    const int part = tid & 3;
    const int node = n0 + nl;

    for (int i = tid; i < (IN_F + PSI_F) * H2; i += 128) ws[i] = w1[i];
    if (tid < H2) b1s[tid] = b1[tid];

    float g[H2];
#pragma unroll
    for (int r = 0; r < H2; r++) g[r] = 0.f;

    for (int cf = 0; cf < 4; cf++) {
        __syncthreads();
        for (int idx = tid; idx < 32 * 32; idx += 128) {
            int nn = idx >> 5, f = idx & 31;
            xs[nn * 33 + f] = nodes[(size_t)(n0 + nn) * IN_F + cf * 32 + f];
        }
        __syncthreads();
#pragma unroll
        for (int f = 0; f < 8; f++) {
            float xv = xs[nl * 33 + part * 8 + f];
            const float* wr = ws + (cf * 32 + part * 8 + f) * H2;
#pragma unroll
            for (int r = 0; r < H2; r++) g[r] = fmaf(xv, wr[r], g[r]);
        }
    }

    // neighbor count
    float cntv = 0.f;
#pragma unroll 4
    for (int jc = 0; jc < JC; jc++)
        cntv += g_part[((size_t)jc * 17 + 16) * NNODES + node];
    float inv = 1.f / cntv;

    // psi features: this thread handles 4 of 16
#pragma unroll
    for (int kk = 0; kk < 4; kk++) {
        int k = part * 4 + kk;
        float s = 0.f;
#pragma unroll 4
        for (int jc = 0; jc < JC; jc++)
            s += g_part[((size_t)jc * 17 + k) * NNODES + node];
        s *= inv;
        const float* wr = ws + (IN_F + k) * H2;
#pragma unroll
        for (int r = 0; r < H2; r++) g[r] = fmaf(s, wr[r], g[r]);
    }

#pragma unroll
    for (int r = 0; r < H2; r++) {
        g[r] += __shfl_xor_sync(0xFFFFFFFFu, g[r], 1);
        g[r] += __shfl_xor_sync(0xFFFFFFFFu, g[r], 2);
    }
    if (part == 0) {
#pragma unroll
        for (int r = 0; r < H2; r++) gs[nl * 26 + r] = fmaxf(g[r] + b1s[r], 0.f);
    }
    __syncthreads();

    // phase 2: thread = output channel; 32 nodes each; coalesced STG
    float w2r[H2];
#pragma unroll
    for (int r = 0; r < H2; r++) w2r[r] = w2[r * OUT_F + tid];
    const float b2v = b2[tid];

#pragma unroll 4
    for (int n = 0; n < 32; n++) {
        float o = b2v;
#pragma unroll
        for (int r = 0; r < H2; r++) o = fmaf(gs[n * 26 + r], w2r[r], o);
        out[(size_t)(n0 + n) * OUT_F + tid] = fmaxf(o, 0.f);
    }
}

// ---------------------------------------------------------------------------
extern "C" void kernel_launch(void* const* d_in, const int* in_sizes, int n_in,
                              void* d_out, int out_size)
{
    const float* nodes  = (const float*)d_in[0];
    const int*   adj    = (const int*)  d_in[1];
    const float* psi_w1 = (const float*)d_in[2];
    const float* psi_b1 = (const float*)d_in[3];
    const float* psi_w2 = (const float*)d_in[4];
    const float* psi_b2 = (const float*)d_in[5];
    const float* fi_w1  = (const float*)d_in[6];
    const float* fi_b1  = (const float*)d_in[7];
    const float* fi_w2  = (const float*)d_in[8];
    const float* fi_b2  = (const float*)d_in[9];
    float* out = (float*)d_out;

    psi_kernel<<<NNODES / 32, 128>>>(nodes, psi_w1, psi_b1, psi_w2, psi_b2);
    agg_kernel<<<dim3(NNODES / (AGG_THREADS * CPT), JC), AGG_THREADS>>>(adj);
    fin_kernel<<<NNODES / 32, 128>>>(nodes, fi_w1, fi_b1, fi_w2, fi_b2, out);
}

// round 5
// speedup vs baseline: 2.0012x; 1.4714x over previous
#include <cuda_runtime.h>
#include <cuda_bf16.h>
#include <cstdint>

#define NN 16384
#define IN_F 128
#define PSI_F 16
#define H1 15
#define H2 25
#define OUT_F 128

#define JB 16                 // partial-sum groups
#define CHK 64                // j per chunk
#define NCH 16                // chunks per CTA (JB*NCH*CHK = 16384)
#define ITILE 128             // i columns per CTA (8 warps x n16)

__device__ __nv_bfloat16 g_hT[PSI_F * NN];             // [f][node] 512 KB
__device__ float g_part[(size_t)JB * 17 * NN];         // [jb][k(0..15 feat,16 cnt)][i] 17.8 MB

// ---------------------------------------------------------------------------
// PTX helpers (all plain sm_80-era PTX; no arch-gated features)
// ---------------------------------------------------------------------------
__device__ __forceinline__ uint32_t smem_u32(const void* p) {
    uint32_t a;
    asm("{ .reg .u64 t; cvta.to.shared.u64 t, %1; cvt.u32.u64 %0, t; }" : "=r"(a) : "l"(p));
    return a;
}
__device__ __forceinline__ void ldm_x4(uint32_t* r, uint32_t addr) {
    asm volatile("ldmatrix.sync.aligned.m8n8.x4.shared.b16 {%0,%1,%2,%3}, [%4];"
                 : "=r"(r[0]), "=r"(r[1]), "=r"(r[2]), "=r"(r[3]) : "r"(addr));
}
__device__ __forceinline__ void ldm_x4_trans(uint32_t* r, uint32_t addr) {
    asm volatile("ldmatrix.sync.aligned.m8n8.x4.trans.shared.b16 {%0,%1,%2,%3}, [%4];"
                 : "=r"(r[0]), "=r"(r[1]), "=r"(r[2]), "=r"(r[3]) : "r"(addr));
}
__device__ __forceinline__ void mma_bf16(float* d, const uint32_t* a,
                                         uint32_t b0, uint32_t b1) {
    asm volatile("mma.sync.aligned.m16n8k16.row.col.f32.bf16.bf16.f32 "
                 "{%0,%1,%2,%3}, {%4,%5,%6,%7}, {%8,%9}, {%0,%1,%2,%3};"
                 : "+f"(d[0]), "+f"(d[1]), "+f"(d[2]), "+f"(d[3])
                 : "r"(a[0]), "r"(a[1]), "r"(a[2]), "r"(a[3]), "r"(b0), "r"(b1));
}

// ---------------------------------------------------------------------------
// Kernel A: psi MLP -> g_hT bf16 [f][node]. 4 thr/node, 64 nodes/block.
// ---------------------------------------------------------------------------
__global__ void __launch_bounds__(256) psi_kernel(
    const float* __restrict__ nodes,
    const float* __restrict__ w1, const float* __restrict__ b1,
    const float* __restrict__ w2, const float* __restrict__ b2)
{
    __shared__ float w1s[IN_F * H1];
    __shared__ float w2s[H1 * PSI_F];
    __shared__ float b1s[H1];
    __shared__ float b2s[PSI_F];
    __shared__ __align__(16) float xs[64 * 132];

    const int tid = threadIdx.x;
    const int n0 = blockIdx.x * 64;
    const int nl = tid >> 2;
    const int part = tid & 3;

    for (int i = tid; i < IN_F * H1; i += 256) w1s[i] = w1[i];
    for (int i = tid; i < H1 * PSI_F; i += 256) w2s[i] = w2[i];
    if (tid < H1) b1s[tid] = b1[tid];
    if (tid >= 32 && tid < 32 + PSI_F) b2s[tid - 32] = b2[tid - 32];

    for (int idx = tid; idx < 64 * 32; idx += 256) {
        int node = idx >> 5, c4 = idx & 31;
        float4 v = reinterpret_cast<const float4*>(nodes + (size_t)(n0 + node) * IN_F)[c4];
        *reinterpret_cast<float4*>(xs + node * 132 + c4 * 4) = v;
    }
    __syncthreads();

    float t[H1];
#pragma unroll
    for (int r = 0; r < H1; r++) t[r] = 0.f;

    const float* xrow = xs + nl * 132 + part * 32;
#pragma unroll 8
    for (int f = 0; f < 32; f++) {
        int fi = (f + part) & 31;
        float xv = xrow[fi];
        const float* wr = w1s + (part * 32 + fi) * H1;
#pragma unroll
        for (int r = 0; r < H1; r++) t[r] = fmaf(xv, wr[r], t[r]);
    }
#pragma unroll
    for (int r = 0; r < H1; r++) {
        t[r] += __shfl_xor_sync(0xFFFFFFFFu, t[r], 1);
        t[r] += __shfl_xor_sync(0xFFFFFFFFu, t[r], 2);
        t[r] = fmaxf(t[r] + b1s[r], 0.f);
    }

    float hv[4];
#pragma unroll
    for (int q = 0; q < 4; q++) hv[q] = b2s[part * 4 + q];
#pragma unroll
    for (int r = 0; r < H1; r++) {
#pragma unroll
        for (int q = 0; q < 4; q++)
            hv[q] = fmaf(t[r], w2s[r * PSI_F + part * 4 + q], hv[q]);
    }
#pragma unroll
    for (int q = 0; q < 4; q++)
        g_hT[(size_t)(part * 4 + q) * NN + n0 + nl] =
            __float2bfloat16(fmaxf(hv[q], 0.f));
}

// ---------------------------------------------------------------------------
// Kernel B: aggregation via mma.sync (bf16 HMMA).
//   psi_out^T[17 x i] += [h^T ; ones] @ A_chunk, per 64-j chunk.
// ---------------------------------------------------------------------------
__global__ void __launch_bounds__(256, 2) agg_kernel(const int* __restrict__ A)
{
    __shared__ __align__(1024) unsigned char Ab[2][16384];  // 64j x 128i bf16, swizzled
    __shared__ __align__(1024) unsigned char Hb[2][2048];   // 16f x 64j  bf16, swizzled

    const int tid = threadIdx.x;
    const int w = tid >> 5, lane = tid & 31;
    const int i0 = blockIdx.x * ITILE;
    const int jb = blockIdx.y;
    const int jbase = jb * NCH * CHK;

    const uint32_t ab0 = smem_u32(Ab[0]);
    const uint32_t hb0 = smem_u32(Hb[0]);

    // conversion-thread coords: 16 j-rows per pass x 16 i-chunks(8 cols)
    const int jrow = tid >> 4;
    const int ic8 = tid & 15;
    const uint32_t swsts = (uint32_t)((ic8 ^ (jrow & 7)) << 4);   // A STS chunk offset

    // h staging coords (threads 0..127)
    const int hf = tid >> 3;           // feature row 0..15
    const int hc = tid & 7;            // 16B chunk 0..7
    const uint32_t hsts = (uint32_t)(hf * 128 + ((hc ^ (hf & 7)) << 4));

    // ldmatrix lane addressing
    const int sub = lane >> 3;
    const int jl = (lane & 7) + ((sub & 1) << 3);               // B: local j row
    const uint32_t boff = (uint32_t)(jl * 256 + (((w * 2 + (sub >> 1)) ^ (jl & 7)) << 4));
    const int hfr = (lane & 7) + ((sub & 1) << 3);              // A(h): feature row
    const int hsub = sub >> 1;

    float dh0[4] = {0, 0, 0, 0}, dh1[4] = {0, 0, 0, 0};
    float dc0[4] = {0, 0, 0, 0}, dc1[4] = {0, 0, 0, 0};
    uint32_t ones[4] = {0x3F803F80u, 0x3F803F80u, 0x3F803F80u, 0x3F803F80u};

    // prefetch chunk 0
    int4 r[8];
    int4 hreg = make_int4(0, 0, 0, 0);
    {
        const size_t base = (size_t)(jbase + jrow) * NN + i0 + ic8 * 8;
#pragma unroll
        for (int s = 0; s < 4; s++) {
            const int4* p = reinterpret_cast<const int4*>(A + base + (size_t)(s * 16) * NN);
            r[2 * s] = p[0];
            r[2 * s + 1] = p[1];
        }
        if (tid < 128)
            hreg = *reinterpret_cast<const int4*>(g_hT + (size_t)hf * NN + jbase + hc * 8);
    }

    for (int c = 0; c < NCH; c++) {
        const int b = c & 1;
        const uint32_t abB = ab0 + (uint32_t)b * 16384;
        const uint32_t hbB = hb0 + (uint32_t)b * 2048;

        // store converted A chunk (int -> bf16: e0*0x3F80 + e1*0x3F800000)
#pragma unroll
        for (int s = 0; s < 4; s++) {
            int4 q0 = r[2 * s], q1 = r[2 * s + 1];
            uint4 v;
            v.x = (uint32_t)q0.x * 0x3F80u + (uint32_t)q0.y * 0x3F800000u;
            v.y = (uint32_t)q0.z * 0x3F80u + (uint32_t)q0.w * 0x3F800000u;
            v.z = (uint32_t)q1.x * 0x3F80u + (uint32_t)q1.y * 0x3F800000u;
            v.w = (uint32_t)q1.z * 0x3F80u + (uint32_t)q1.w * 0x3F800000u;
            asm volatile("st.shared.v4.b32 [%0], {%1,%2,%3,%4};"
                         :: "r"(abB + (uint32_t)((jrow + s * 16) * 256) + swsts),
                            "r"(v.x), "r"(v.y), "r"(v.z), "r"(v.w) : "memory");
        }
        if (tid < 128)
            asm volatile("st.shared.v4.b32 [%0], {%1,%2,%3,%4};"
                         :: "r"(hbB + hsts),
                            "r"((uint32_t)hreg.x), "r"((uint32_t)hreg.y),
                            "r"((uint32_t)hreg.z), "r"((uint32_t)hreg.w) : "memory");

        // prefetch next chunk while this one computes
        if (c + 1 < NCH) {
            const size_t base = (size_t)(jbase + (c + 1) * CHK + jrow) * NN + i0 + ic8 * 8;
#pragma unroll
            for (int s = 0; s < 4; s++) {
                const int4* p = reinterpret_cast<const int4*>(A + base + (size_t)(s * 16) * NN);
                r[2 * s] = p[0];
                r[2 * s + 1] = p[1];
            }
            if (tid < 128)
                hreg = *reinterpret_cast<const int4*>(
                    g_hT + (size_t)hf * NN + jbase + (c + 1) * CHK + hc * 8);
        }

        __syncthreads();

#pragma unroll
        for (int ks = 0; ks < 4; ks++) {
            uint32_t af[4], bf[4];
            ldm_x4(af, hbB + (uint32_t)(hfr * 128 + (((ks * 2 + hsub) ^ (hfr & 7)) << 4)));
            ldm_x4_trans(bf, abB + (uint32_t)(ks * 4096) + boff);
            mma_bf16(dh0, af, bf[0], bf[1]);
            mma_bf16(dh1, af, bf[2], bf[3]);
            mma_bf16(dc0, ones, bf[0], bf[1]);
            mma_bf16(dc1, ones, bf[2], bf[3]);
        }
    }

    // write partials: D frag -> g_part[jb][k][i]
    const int rrow = lane >> 2;
    const int ncol = (lane & 3) * 2;
    const size_t pb = (size_t)jb * 17 * NN + i0 + w * 16;
    // n-tile 0
    g_part[pb + (size_t)rrow * NN + ncol]           = dh0[0];
    g_part[pb + (size_t)rrow * NN + ncol + 1]       = dh0[1];
    g_part[pb + (size_t)(rrow + 8) * NN + ncol]     = dh0[2];
    g_part[pb + (size_t)(rrow + 8) * NN + ncol + 1] = dh0[3];
    // n-tile 1
    g_part[pb + (size_t)rrow * NN + 8 + ncol]           = dh1[0];
    g_part[pb + (size_t)rrow * NN + 8 + ncol + 1]       = dh1[1];
    g_part[pb + (size_t)(rrow + 8) * NN + 8 + ncol]     = dh1[2];
    g_part[pb + (size_t)(rrow + 8) * NN + 8 + ncol + 1] = dh1[3];
    // counts (rows of ones-D all equal; lanes 0..3 cover n 0..7 per tile)
    if (lane < 4) {
        g_part[pb + (size_t)16 * NN + ncol]         = dc0[0];
        g_part[pb + (size_t)16 * NN + ncol + 1]     = dc0[1];
        g_part[pb + (size_t)16 * NN + 8 + ncol]     = dc1[0];
        g_part[pb + (size_t)16 * NN + 8 + ncol + 1] = dc1[1];
    }
}

// ---------------------------------------------------------------------------
// Kernel C: reduce partials + fi MLP. 4 thr/node phase 1, 32 nodes/block.
// ---------------------------------------------------------------------------
__global__ void __launch_bounds__(128) fin_kernel(
    const float* __restrict__ nodes,
    const float* __restrict__ w1, const float* __restrict__ b1,
    const float* __restrict__ w2, const float* __restrict__ b2,
    float* __restrict__ out)
{
    __shared__ float ws[(IN_F + PSI_F) * H2];
    __shared__ float b1s[H2];
    __shared__ float xs[32 * 33];
    __shared__ float gs[32 * 26];

    const int tid = threadIdx.x;
    const int n0 = blockIdx.x * 32;
    const int nl = tid >> 2;
    const int part = tid & 3;
    const int node = n0 + nl;

    for (int i = tid; i < (IN_F + PSI_F) * H2; i += 128) ws[i] = w1[i];
    if (tid < H2) b1s[tid] = b1[tid];

    float g[H2];
#pragma unroll
    for (int r = 0; r < H2; r++) g[r] = 0.f;

    for (int cf = 0; cf < 4; cf++) {
        __syncthreads();
        for (int idx = tid; idx < 32 * 32; idx += 128) {
            int nn2 = idx >> 5, f = idx & 31;
            xs[nn2 * 33 + f] = nodes[(size_t)(n0 + nn2) * IN_F + cf * 32 + f];
        }
        __syncthreads();
#pragma unroll
        for (int f = 0; f < 8; f++) {
            float xv = xs[nl * 33 + part * 8 + f];
            const float* wr = ws + (cf * 32 + part * 8 + f) * H2;
#pragma unroll
            for (int r = 0; r < H2; r++) g[r] = fmaf(xv, wr[r], g[r]);
        }
    }

    float cntv = 0.f;
#pragma unroll 4
    for (int jc = 0; jc < JB; jc++)
        cntv += g_part[((size_t)jc * 17 + 16) * NN + node];
    float inv = 1.f / cntv;

#pragma unroll
    for (int kk = 0; kk < 4; kk++) {
        int k = part * 4 + kk;
        float s = 0.f;
#pragma unroll 4
        for (int jc = 0; jc < JB; jc++)
            s += g_part[((size_t)jc * 17 + k) * NN + node];
        s *= inv;
        const float* wr = ws + (IN_F + k) * H2;
#pragma unroll
        for (int r = 0; r < H2; r++) g[r] = fmaf(s, wr[r], g[r]);
    }

#pragma unroll
    for (int r = 0; r < H2; r++) {
        g[r] += __shfl_xor_sync(0xFFFFFFFFu, g[r], 1);
        g[r] += __shfl_xor_sync(0xFFFFFFFFu, g[r], 2);
    }
    if (part == 0) {
#pragma unroll
        for (int r = 0; r < H2; r++) gs[nl * 26 + r] = fmaxf(g[r] + b1s[r], 0.f);
    }
    __syncthreads();

    float w2r[H2];
#pragma unroll
    for (int r = 0; r < H2; r++) w2r[r] = w2[r * OUT_F + tid];
    const float b2v = b2[tid];

#pragma unroll 4
    for (int n = 0; n < 32; n++) {
        float o = b2v;
#pragma unroll
        for (int r = 0; r < H2; r++) o = fmaf(gs[n * 26 + r], w2r[r], o);
        out[(size_t)(n0 + n) * OUT_F + tid] = fmaxf(o, 0.f);
    }
}

// ---------------------------------------------------------------------------
extern "C" void kernel_launch(void* const* d_in, const int* in_sizes, int n_in,
                              void* d_out, int out_size)
{
    const float* nodes  = (const float*)d_in[0];
    const int*   adj    = (const int*)  d_in[1];
    const float* psi_w1 = (const float*)d_in[2];
    const float* psi_b1 = (const float*)d_in[3];
    const float* psi_w2 = (const float*)d_in[4];
    const float* psi_b2 = (const float*)d_in[5];
    const float* fi_w1  = (const float*)d_in[6];
    const float* fi_b1  = (const float*)d_in[7];
    const float* fi_w2  = (const float*)d_in[8];
    const float* fi_b2  = (const float*)d_in[9];
    float* out = (float*)d_out;

    psi_kernel<<<NN / 64, 256>>>(nodes, psi_w1, psi_b1, psi_w2, psi_b2);
    agg_kernel<<<dim3(NN / ITILE, JB), 256>>>(adj);
    fin_kernel<<<NN / 32, 128>>>(nodes, fi_w1, fi_b1, fi_w2, fi_b2, out);
}

// round 6
// speedup vs baseline: 2.0121x; 1.0054x over previous
#include <cuda_runtime.h>
#include <cuda_bf16.h>
#include <cstdint>

#define NN 16384
#define IN_F 128
#define PSI_F 16
#define H1 15
#define H2 25
#define OUT_F 128

#define JB 8                  // partial-sum groups
#define CHK 64                // j per chunk
#define NCH 32                // chunks per CTA (JB*NCH*CHK = 16384)
#define ITILE 128             // i columns per CTA (8 warps x n16)

__device__ __nv_bfloat16 g_hT[PSI_F * NN];             // [f][node] 512 KB
__device__ float g_part[(size_t)JB * 17 * NN];         // [jb][k(0..15 feat,16 cnt)][i] 8.9 MB

// ---------------------------------------------------------------------------
// PTX helpers (plain sm_80-era PTX)
// ---------------------------------------------------------------------------
__device__ __forceinline__ uint32_t smem_u32(const void* p) {
    uint32_t a;
    asm("{ .reg .u64 t; cvta.to.shared.u64 t, %1; cvt.u32.u64 %0, t; }" : "=r"(a) : "l"(p));
    return a;
}
__device__ __forceinline__ void ldm_x4(uint32_t* r, uint32_t addr) {
    asm volatile("ldmatrix.sync.aligned.m8n8.x4.shared.b16 {%0,%1,%2,%3}, [%4];"
                 : "=r"(r[0]), "=r"(r[1]), "=r"(r[2]), "=r"(r[3]) : "r"(addr));
}
__device__ __forceinline__ void ldm_x4_trans(uint32_t* r, uint32_t addr) {
    asm volatile("ldmatrix.sync.aligned.m8n8.x4.trans.shared.b16 {%0,%1,%2,%3}, [%4];"
                 : "=r"(r[0]), "=r"(r[1]), "=r"(r[2]), "=r"(r[3]) : "r"(addr));
}
__device__ __forceinline__ void mma_bf16(float* d, const uint32_t* a,
                                         uint32_t b0, uint32_t b1) {
    asm volatile("mma.sync.aligned.m16n8k16.row.col.f32.bf16.bf16.f32 "
                 "{%0,%1,%2,%3}, {%4,%5,%6,%7}, {%8,%9}, {%0,%1,%2,%3};"
                 : "+f"(d[0]), "+f"(d[1]), "+f"(d[2]), "+f"(d[3])
                 : "r"(a[0]), "r"(a[1]), "r"(a[2]), "r"(a[3]), "r"(b0), "r"(b1));
}

// ---------------------------------------------------------------------------
// Kernel A: psi MLP -> g_hT bf16 [f][node]. 8 thr/node, 32 nodes/block.
// W1 in smem with stride-20 rows -> conflict-free LDS.128.
// ---------------------------------------------------------------------------
__global__ void __launch_bounds__(256) psi_kernel(
    const float* __restrict__ nodes,
    const float* __restrict__ w1, const float* __restrict__ b1,
    const float* __restrict__ w2, const float* __restrict__ b2)
{
    __shared__ __align__(16) float w1p[IN_F * 20];     // 10.2 KB
    __shared__ float w2s[H1 * PSI_F];
    __shared__ float b1s[H1];
    __shared__ float b2s[PSI_F];
    __shared__ __nv_bfloat16 hsm[PSI_F * 33];

    const int tid = threadIdx.x;
    const int n0 = blockIdx.x * 32;
    const int nl = tid >> 3;       // local node 0..31
    const int part = tid & 7;      // feature eighth

    for (int i = tid; i < IN_F * H1; i += 256) {
        int f = i / H1, r = i - f * H1;
        w1p[f * 20 + r] = w1[i];
    }
    if (tid < IN_F) w1p[tid * 20 + 15] = 0.f;          // dummy 16th weight
    for (int i = tid; i < H1 * PSI_F; i += 256) w2s[i] = w2[i];
    if (tid < H1) b1s[tid] = b1[tid];
    if (tid >= 32 && tid < 32 + PSI_F) b2s[tid - 32] = b2[tid - 32];

    // x features part, part+8, ..., part+120 directly from global (coalesced 32B)
    const float* xp = nodes + (size_t)(n0 + nl) * IN_F + part;
    float xv[16];
#pragma unroll
    for (int f = 0; f < 16; f++) xv[f] = xp[f * 8];
    __syncthreads();

    float t[16];
#pragma unroll
    for (int r = 0; r < 16; r++) t[r] = 0.f;

#pragma unroll
    for (int f = 0; f < 16; f++) {
        const float4* wr = reinterpret_cast<const float4*>(w1p + (part + 8 * f) * 20);
#pragma unroll
        for (int q = 0; q < 4; q++) {
            float4 wq = wr[q];
            t[q * 4 + 0] = fmaf(xv[f], wq.x, t[q * 4 + 0]);
            t[q * 4 + 1] = fmaf(xv[f], wq.y, t[q * 4 + 1]);
            t[q * 4 + 2] = fmaf(xv[f], wq.z, t[q * 4 + 2]);
            t[q * 4 + 3] = fmaf(xv[f], wq.w, t[q * 4 + 3]);
        }
    }
#pragma unroll
    for (int r = 0; r < H1; r++) {
        t[r] += __shfl_xor_sync(0xFFFFFFFFu, t[r], 1);
        t[r] += __shfl_xor_sync(0xFFFFFFFFu, t[r], 2);
        t[r] += __shfl_xor_sync(0xFFFFFFFFu, t[r], 4);
        t[r] = fmaxf(t[r] + b1s[r], 0.f);
    }

    // layer 2: this thread produces outputs 2*part, 2*part+1
    float hv0 = b2s[2 * part], hv1 = b2s[2 * part + 1];
#pragma unroll
    for (int r = 0; r < H1; r++) {
        hv0 = fmaf(t[r], w2s[r * PSI_F + 2 * part], hv0);
        hv1 = fmaf(t[r], w2s[r * PSI_F + 2 * part + 1], hv1);
    }
    hsm[(2 * part) * 33 + nl]     = __float2bfloat16(fmaxf(hv0, 0.f));
    hsm[(2 * part + 1) * 33 + nl] = __float2bfloat16(fmaxf(hv1, 0.f));
    __syncthreads();

    // cooperative k-major store: 16 k x 32 nodes
    if (tid < 128) {
        int k = tid & 15, h = tid >> 4;                // h: 4-node chunk 0..7
        uint32_t lo = (uint32_t)__bfloat16_as_ushort(hsm[k * 33 + 4 * h + 0])
                    | ((uint32_t)__bfloat16_as_ushort(hsm[k * 33 + 4 * h + 1]) << 16);
        uint32_t hi = (uint32_t)__bfloat16_as_ushort(hsm[k * 33 + 4 * h + 2])
                    | ((uint32_t)__bfloat16_as_ushort(hsm[k * 33 + 4 * h + 3]) << 16);
        *reinterpret_cast<uint2*>(g_hT + (size_t)k * NN + n0 + 4 * h) = make_uint2(lo, hi);
    }
}

// ---------------------------------------------------------------------------
// Kernel B: aggregation via mma.sync (bf16 HMMA).
//   psi_out^T[17 x i] += [h^T ; ones] @ A_chunk, per 64-j chunk.
// ---------------------------------------------------------------------------
__global__ void __launch_bounds__(256, 2) agg_kernel(const int* __restrict__ A)
{
    __shared__ __align__(1024) unsigned char Ab[2][16384];  // 64j x 128i bf16, swizzled
    __shared__ __align__(1024) unsigned char Hb[2][2048];   // 16f x 64j  bf16, swizzled

    const int tid = threadIdx.x;
    const int w = tid >> 5, lane = tid & 31;
    const int i0 = blockIdx.x * ITILE;
    const int jb = blockIdx.y;
    const int jbase = jb * NCH * CHK;

    const uint32_t ab0 = smem_u32(Ab[0]);
    const uint32_t hb0 = smem_u32(Hb[0]);

    const int jrow = tid >> 4;
    const int ic8 = tid & 15;
    const uint32_t swsts = (uint32_t)((ic8 ^ (jrow & 7)) << 4);

    const int hf = tid >> 3;
    const int hc = tid & 7;
    const uint32_t hsts = (uint32_t)(hf * 128 + ((hc ^ (hf & 7)) << 4));

    const int sub = lane >> 3;
    const int jl = (lane & 7) + ((sub & 1) << 3);
    const uint32_t boff = (uint32_t)(jl * 256 + (((w * 2 + (sub >> 1)) ^ (jl & 7)) << 4));
    const int hfr = (lane & 7) + ((sub & 1) << 3);
    const int hsub = sub >> 1;

    float dh0[4] = {0, 0, 0, 0}, dh1[4] = {0, 0, 0, 0};
    float dc0[4] = {0, 0, 0, 0}, dc1[4] = {0, 0, 0, 0};
    uint32_t ones[4] = {0x3F803F80u, 0x3F803F80u, 0x3F803F80u, 0x3F803F80u};

    int4 r[8];
    int4 hreg = make_int4(0, 0, 0, 0);
    {
        const size_t base = (size_t)(jbase + jrow) * NN + i0 + ic8 * 8;
#pragma unroll
        for (int s = 0; s < 4; s++) {
            const int4* p = reinterpret_cast<const int4*>(A + base + (size_t)(s * 16) * NN);
            r[2 * s] = p[0];
            r[2 * s + 1] = p[1];
        }
        if (tid < 128)
            hreg = *reinterpret_cast<const int4*>(g_hT + (size_t)hf * NN + jbase + hc * 8);
    }

    for (int c = 0; c < NCH; c++) {
        const int b = c & 1;
        const uint32_t abB = ab0 + (uint32_t)b * 16384;
        const uint32_t hbB = hb0 + (uint32_t)b * 2048;

#pragma unroll
        for (int s = 0; s < 4; s++) {
            int4 q0 = r[2 * s], q1 = r[2 * s + 1];
            uint4 v;
            v.x = (uint32_t)q0.x * 0x3F80u + (uint32_t)q0.y * 0x3F800000u;
            v.y = (uint32_t)q0.z * 0x3F80u + (uint32_t)q0.w * 0x3F800000u;
            v.z = (uint32_t)q1.x * 0x3F80u + (uint32_t)q1.y * 0x3F800000u;
            v.w = (uint32_t)q1.z * 0x3F80u + (uint32_t)q1.w * 0x3F800000u;
            asm volatile("st.shared.v4.b32 [%0], {%1,%2,%3,%4};"
                         :: "r"(abB + (uint32_t)((jrow + s * 16) * 256) + swsts),
                            "r"(v.x), "r"(v.y), "r"(v.z), "r"(v.w) : "memory");
        }
        if (tid < 128)
            asm volatile("st.shared.v4.b32 [%0], {%1,%2,%3,%4};"
                         :: "r"(hbB + hsts),
                            "r"((uint32_t)hreg.x), "r"((uint32_t)hreg.y),
                            "r"((uint32_t)hreg.z), "r"((uint32_t)hreg.w) : "memory");

        if (c + 1 < NCH) {
            const size_t base = (size_t)(jbase + (c + 1) * CHK + jrow) * NN + i0 + ic8 * 8;
#pragma unroll
            for (int s = 0; s < 4; s++) {
                const int4* p = reinterpret_cast<const int4*>(A + base + (size_t)(s * 16) * NN);
                r[2 * s] = p[0];
                r[2 * s + 1] = p[1];
            }
            if (tid < 128)
                hreg = *reinterpret_cast<const int4*>(
                    g_hT + (size_t)hf * NN + jbase + (c + 1) * CHK + hc * 8);
        }

        __syncthreads();

#pragma unroll
        for (int ks = 0; ks < 4; ks++) {
            uint32_t af[4], bf[4];
            ldm_x4(af, hbB + (uint32_t)(hfr * 128 + (((ks * 2 + hsub) ^ (hfr & 7)) << 4)));
            ldm_x4_trans(bf, abB + (uint32_t)(ks * 4096) + boff);
            mma_bf16(dh0, af, bf[0], bf[1]);
            mma_bf16(dh1, af, bf[2], bf[3]);
            mma_bf16(dc0, ones, bf[0], bf[1]);
            mma_bf16(dc1, ones, bf[2], bf[3]);
        }
    }

    const int rrow = lane >> 2;
    const int ncol = (lane & 3) * 2;
    const size_t pb = (size_t)jb * 17 * NN + i0 + w * 16;
    g_part[pb + (size_t)rrow * NN + ncol]           = dh0[0];
    g_part[pb + (size_t)rrow * NN + ncol + 1]       = dh0[1];
    g_part[pb + (size_t)(rrow + 8) * NN + ncol]     = dh0[2];
    g_part[pb + (size_t)(rrow + 8) * NN + ncol + 1] = dh0[3];
    g_part[pb + (size_t)rrow * NN + 8 + ncol]           = dh1[0];
    g_part[pb + (size_t)rrow * NN + 8 + ncol + 1]       = dh1[1];
    g_part[pb + (size_t)(rrow + 8) * NN + 8 + ncol]     = dh1[2];
    g_part[pb + (size_t)(rrow + 8) * NN + 8 + ncol + 1] = dh1[3];
    if (lane < 4) {
        g_part[pb + (size_t)16 * NN + ncol]         = dc0[0];
        g_part[pb + (size_t)16 * NN + ncol + 1]     = dc0[1];
        g_part[pb + (size_t)16 * NN + 8 + ncol]     = dc1[0];
        g_part[pb + (size_t)16 * NN + 8 + ncol + 1] = dc1[1];
    }
}

// ---------------------------------------------------------------------------
// Kernel C: reduce partials + fi MLP. 8 thr/node phase 1, 32 nodes/block.
// W1 in smem with stride-28 rows -> conflict-free LDS.128.
// ---------------------------------------------------------------------------
__global__ void __launch_bounds__(256) fin_kernel(
    const float* __restrict__ nodes,
    const float* __restrict__ w1, const float* __restrict__ b1,
    const float* __restrict__ w2, const float* __restrict__ b2,
    float* __restrict__ out)
{
    __shared__ __align__(16) float wp[(IN_F + PSI_F) * 28];   // 16.1 KB
    __shared__ float b1s[H2];
    __shared__ float gs[32 * 26];

    const int tid = threadIdx.x;
    const int n0 = blockIdx.x * 32;
    const int nl = tid >> 3;
    const int part = tid & 7;
    const int node = n0 + nl;

    for (int i = tid; i < (IN_F + PSI_F) * H2; i += 256) {
        int f = i / H2, r = i - f * H2;
        wp[f * 28 + r] = w1[i];
    }
    for (int i = tid; i < IN_F + PSI_F; i += 256) {
        wp[i * 28 + 25] = 0.f; wp[i * 28 + 26] = 0.f; wp[i * 28 + 27] = 0.f;
    }
    if (tid < H2) b1s[tid] = b1[tid];

    const float* xp = nodes + (size_t)node * IN_F + part;
    float xv[16];
#pragma unroll
    for (int f = 0; f < 16; f++) xv[f] = xp[f * 8];
    __syncthreads();

    float g[28];
#pragma unroll
    for (int r = 0; r < 28; r++) g[r] = 0.f;

#pragma unroll
    for (int f = 0; f < 16; f++) {
        const float4* wr = reinterpret_cast<const float4*>(wp + (part + 8 * f) * 28);
#pragma unroll
        for (int q = 0; q < 7; q++) {
            float4 wq = wr[q];
            g[q * 4 + 0] = fmaf(xv[f], wq.x, g[q * 4 + 0]);
            g[q * 4 + 1] = fmaf(xv[f], wq.y, g[q * 4 + 1]);
            g[q * 4 + 2] = fmaf(xv[f], wq.z, g[q * 4 + 2]);
            g[q * 4 + 3] = fmaf(xv[f], wq.w, g[q * 4 + 3]);
        }
    }

    // psi features: this thread handles 2 of 16
    float cntv = 0.f;
#pragma unroll
    for (int jc = 0; jc < JB; jc++)
        cntv += g_part[((size_t)jc * 17 + 16) * NN + node];
    float inv = 1.f / cntv;

#pragma unroll
    for (int kk = 0; kk < 2; kk++) {
        int k = 2 * part + kk;
        float s = 0.f;
#pragma unroll
        for (int jc = 0; jc < JB; jc++)
            s += g_part[((size_t)jc * 17 + k) * NN + node];
        s *= inv;
        const float4* wr = reinterpret_cast<const float4*>(wp + (IN_F + k) * 28);
#pragma unroll
        for (int q = 0; q < 7; q++) {
            float4 wq = wr[q];
            g[q * 4 + 0] = fmaf(s, wq.x, g[q * 4 + 0]);
            g[q * 4 + 1] = fmaf(s, wq.y, g[q * 4 + 1]);
            g[q * 4 + 2] = fmaf(s, wq.z, g[q * 4 + 2]);
            g[q * 4 + 3] = fmaf(s, wq.w, g[q * 4 + 3]);
        }
    }

#pragma unroll
    for (int r = 0; r < H2; r++) {
        g[r] += __shfl_xor_sync(0xFFFFFFFFu, g[r], 1);
        g[r] += __shfl_xor_sync(0xFFFFFFFFu, g[r], 2);
        g[r] += __shfl_xor_sync(0xFFFFFFFFu, g[r], 4);
    }
    if (part == 0) {
#pragma unroll
        for (int r = 0; r < H2; r++) gs[nl * 26 + r] = fmaxf(g[r] + b1s[r], 0.f);
    }
    __syncthreads();

    // phase 2: thread = (channel, node half); coalesced STG
    const int ch = tid & 127;
    const int nh = tid >> 7;
    float w2r[H2];
#pragma unroll
    for (int r = 0; r < H2; r++) w2r[r] = w2[r * OUT_F + ch];
    const float b2v = b2[ch];

#pragma unroll 4
    for (int n = 0; n < 16; n++) {
        int nn = nh * 16 + n;
        float o = b2v;
#pragma unroll
        for (int r = 0; r < H2; r++) o = fmaf(gs[nn * 26 + r], w2r[r], o);
        out[(size_t)(n0 + nn) * OUT_F + ch] = fmaxf(o, 0.f);
    }
}

// ---------------------------------------------------------------------------
extern "C" void kernel_launch(void* const* d_in, const int* in_sizes, int n_in,
                              void* d_out, int out_size)
{
    const float* nodes  = (const float*)d_in[0];
    const int*   adj    = (const int*)  d_in[1];
    const float* psi_w1 = (const float*)d_in[2];
    const float* psi_b1 = (const float*)d_in[3];
    const float* psi_w2 = (const float*)d_in[4];
    const float* psi_b2 = (const float*)d_in[5];
    const float* fi_w1  = (const float*)d_in[6];
    const float* fi_b1  = (const float*)d_in[7];
    const float* fi_w2  = (const float*)d_in[8];
    const float* fi_b2  = (const float*)d_in[9];
    float* out = (float*)d_out;

    psi_kernel<<<NN / 32, 256>>>(nodes, psi_w1, psi_b1, psi_w2, psi_b2);
    agg_kernel<<<dim3(NN / ITILE, JB), 256>>>(adj);
    fin_kernel<<<NN / 32, 256>>>(nodes, fi_w1, fi_b1, fi_w2, fi_b2, out);
}